// round 11
// baseline (speedup 1.0000x reference)
#include <cuda_runtime.h>
#include <cuda_fp16.h>
#include <cstdint>
#include <math_constants.h>

// Problem dims (fixed per reference)
#define DM   1024      // d_model
#define DF   4096      // d_ff
#define MROWS 16384    // 4 * 4096

// ---------------------------------------------------------------------------
// Scratch (allocation-free: __device__ globals)
// ---------------------------------------------------------------------------
__device__ float  g_scores[(size_t)MROWS * DF];   // 256 MB fp32 logits
__device__ __half g_phi[(size_t)MROWS * DF];      // probs (single fp16)
__device__ __half g_xhi[(size_t)MROWS * DM];      // rmsnorm(x) hi
__device__ __half g_xlo[(size_t)MROWS * DM];      // rmsnorm(x) lo
__device__ __half g_whi[(size_t)DF * DM];         // rmsnorm(w) hi
__device__ __half g_wlo[(size_t)DF * DM];         // rmsnorm(w) lo
__device__ __half g_wthi[(size_t)DM * DF];        // W^T (raw w) [d][c]

// ---------------------------------------------------------------------------
// PTX helpers
// ---------------------------------------------------------------------------
__device__ __forceinline__ uint32_t smem_u32_of(const void* p) {
    uint32_t a;
    asm("{ .reg .u64 t; cvta.to.shared.u64 t, %1; cvt.u32.u64 %0, t; }" : "=r"(a) : "l"(p));
    return a;
}

__device__ __forceinline__ void cp16(uint32_t s, const void* g) {
    asm volatile("cp.async.cg.shared.global [%0], [%1], 16;" :: "r"(s), "l"(g));
}

__device__ __forceinline__ void ldsm4(uint32_t* r, uint32_t a) {
    asm volatile("ldmatrix.sync.aligned.m8n8.x4.shared.b16 {%0,%1,%2,%3}, [%4];"
                 : "=r"(r[0]), "=r"(r[1]), "=r"(r[2]), "=r"(r[3]) : "r"(a));
}

__device__ __forceinline__ void mma16816(float* d, const uint32_t* a, const uint32_t* b) {
    asm volatile(
        "mma.sync.aligned.m16n8k16.row.col.f32.f16.f16.f32 "
        "{%0,%1,%2,%3}, {%4,%5,%6,%7}, {%8,%9}, {%0,%1,%2,%3};"
        : "+f"(d[0]), "+f"(d[1]), "+f"(d[2]), "+f"(d[3])
        : "r"(a[0]), "r"(a[1]), "r"(a[2]), "r"(a[3]), "r"(b[0]), "r"(b[1]));
}

// f16-accumulator variant (2-reg D fragment; same thread/element mapping)
__device__ __forceinline__ void mma16816h(uint32_t* d, const uint32_t* a, const uint32_t* b) {
    asm volatile(
        "mma.sync.aligned.m16n8k16.row.col.f16.f16.f16.f16 "
        "{%0,%1}, {%2,%3,%4,%5}, {%6,%7}, {%0,%1};"
        : "+r"(d[0]), "+r"(d[1])
        : "r"(a[0]), "r"(a[1]), "r"(a[2]), "r"(a[3]), "r"(b[0]), "r"(b[1]));
}

// ---------------------------------------------------------------------------
// Kernel: fused per-row rmsnorm + fp16 hi/lo split.
// ---------------------------------------------------------------------------
__device__ __forceinline__ void split2h(float v, __half& h, __half& l) {
    h = __float2half_rn(v);
    l = __float2half_rn(v - __half2float(h));
}

__global__ __launch_bounds__(256) void rms_split_kernel(
    const float* __restrict__ src,
    __half* __restrict__ hi, __half* __restrict__ lo)
{
    const int row = blockIdx.x;
    const int tid = threadIdx.x;
    const size_t base = (size_t)row * DM;

    float4 v = *(const float4*)(src + base + tid * 4);
    float ss = v.x * v.x + v.y * v.y + v.z * v.z + v.w * v.w;

    __shared__ float red[256];
    red[tid] = ss;
    __syncthreads();
    #pragma unroll
    for (int off = 128; off > 0; off >>= 1) {
        if (tid < off) red[tid] += red[tid + off];
        __syncthreads();
    }
    const float s = rsqrtf(red[0] * (1.0f / DM) + 1e-6f);

    __half h0, h1, h2, h3, l0, l1, l2, l3;
    split2h(v.x * s, h0, l0); split2h(v.y * s, h1, l1);
    split2h(v.z * s, h2, l2); split2h(v.w * s, h3, l3);
    __half2* H = (__half2*)(hi + base + tid * 4);
    __half2* L = (__half2*)(lo + base + tid * 4);
    H[0] = __halves2half2(h0, h1); H[1] = __halves2half2(h2, h3);
    L[0] = __halves2half2(l0, l1); L[1] = __halves2half2(l2, l3);
}

// ---------------------------------------------------------------------------
// Kernel: transpose  W[c,d] -> Wt[d,c]  (raw w, single fp16)
// ---------------------------------------------------------------------------
__global__ void wt_kernel(const float* __restrict__ w, __half* __restrict__ th)
{
    __shared__ float t[32][33];
    const int c = blockIdx.y * 32 + threadIdx.y;
    const int d = blockIdx.x * 32 + threadIdx.x;
    t[threadIdx.y][threadIdx.x] = w[(size_t)c * DM + d];
    __syncthreads();
    const int dd = blockIdx.x * 32 + threadIdx.y;
    const int cc = blockIdx.y * 32 + threadIdx.x;
    th[(size_t)dd * DF + cc] = __float2half_rn(t[threadIdx.x][threadIdx.y]);
}

// ---------------------------------------------------------------------------
// Kernel: row softmax over 4096, emits single fp16 probs
// ---------------------------------------------------------------------------
__global__ __launch_bounds__(256) void softmax_h(const float* __restrict__ S,
                                                 __half* __restrict__ PH)
{
    const int row = blockIdx.x;
    const int tid = threadIdx.x;
    const float* p = S + (size_t)row * DF + tid * 16;

    float v[16];
    #pragma unroll
    for (int j = 0; j < 4; j++) {
        float4 t = *(const float4*)(p + j * 4);
        v[j * 4 + 0] = t.x; v[j * 4 + 1] = t.y;
        v[j * 4 + 2] = t.z; v[j * 4 + 3] = t.w;
    }
    float lm = v[0];
    #pragma unroll
    for (int j = 1; j < 16; j++) lm = fmaxf(lm, v[j]);

    __shared__ float red[256];
    red[tid] = lm;
    __syncthreads();
    #pragma unroll
    for (int off = 128; off > 0; off >>= 1) {
        if (tid < off) red[tid] = fmaxf(red[tid], red[tid + off]);
        __syncthreads();
    }
    const float m = red[0];
    __syncthreads();

    float ls = 0.f;
    #pragma unroll
    for (int j = 0; j < 16; j++) {
        v[j] = __expf(v[j] - m);
        ls += v[j];
    }
    red[tid] = ls;
    __syncthreads();
    #pragma unroll
    for (int off = 128; off > 0; off >>= 1) {
        if (tid < off) red[tid] += red[tid + off];
        __syncthreads();
    }
    const float inv = 1.0f / red[0];

    __half2* ph2 = (__half2*)(PH + (size_t)row * DF + tid * 16);
    #pragma unroll
    for (int j = 0; j < 8; j++) {
        ph2[j] = __halves2half2(__float2half_rn(v[2 * j] * inv),
                                __float2half_rn(v[2 * j + 1] * inv));
    }
}

// ---------------------------------------------------------------------------
// GEMM1: split-fp16 NT GEMM, 512 threads / 16 warps, warp tile 32x32.
//   main  : Ah*Bh  f32 acc;  cross: Ah*Bl + Al*Bh shared f16 acc.
// CTA 128x128, BK=64, 3-stage cp.async ring, ONE barrier per kt.
// Row pitch 144 B (72 halfs): bank step 4 per row -> conflict-free ldmatrix.
// Stage 73728 B: Ah@0 | Al@18432 | Bh@36864 | Bl@55296 (each 128x144).
// Ring safety: load at iter kt writes slot (kt+2)%3 == (kt-1)%3; all warps
// passed the top barrier of kt, hence finished computing kt-1.
// ---------------------------------------------------------------------------
#define PITCH   144
#define PLANE   (128 * PITCH)          // 18432
#define STAGEB  (4 * PLANE)            // 73728
#define GSMEM   (3 * STAGEB)           // 221184

__global__ __launch_bounds__(512, 1) void gemm_hsplit(
    const __half* __restrict__ Ah, const __half* __restrict__ Al,
    const __half* __restrict__ Bh, const __half* __restrict__ Bl,
    float* __restrict__ C, int lda, int ldb, int ldc, int KT)
{
    extern __shared__ __align__(16) char smem[];
    const uint32_t sbase = smem_u32_of(smem);
    const int tid  = threadIdx.x;
    const int lane = tid & 31;
    const int wid  = tid >> 5;           // 0..15
    const int wm   = (wid >> 2) * 32;    // 0,32,64,96
    const int wn   = (wid & 3) * 32;     // 0,32,64,96
    const int bm   = blockIdx.y * 128;
    const int bn   = blockIdx.x * 128;

    // loader: 512 threads, each covers 2x16B chunks per 128B row-span per plane
    const int lr = tid >> 2;             // 0..127
    const int lc = tid & 3;              // 16B chunk index (covers first 64B; +64B second)
    const __half* pAh = Ah + (size_t)(bm + lr) * lda + lc * 8;
    const __half* pAl = Al + (size_t)(bm + lr) * lda + lc * 8;
    const __half* pBh = Bh + (size_t)(bn + lr) * ldb + lc * 8;
    const __half* pBl = Bl + (size_t)(bn + lr) * ldb + lc * 8;
    const uint32_t so = lr * PITCH + lc * 16;

    float    accm[2][4][4];   // hi*hi, f32 acc
    uint32_t accx[2][4][2];   // cross, f16 acc
    #pragma unroll
    for (int i = 0; i < 2; i++)
        #pragma unroll
        for (int j = 0; j < 4; j++) {
            #pragma unroll
            for (int k = 0; k < 4; k++) accm[i][j][k] = 0.f;
            accx[i][j][0] = 0u; accx[i][j][1] = 0u;
        }

#define LOAD_STAGE(kt, slot)                                                  \
    do {                                                                      \
        const int _k0 = (kt) * 64;                                            \
        const uint32_t _sb = sbase + (slot) * STAGEB + so;                    \
        cp16(_sb + 0 * PLANE,      pAh + _k0);                                \
        cp16(_sb + 0 * PLANE + 64, pAh + _k0 + 32);                           \
        cp16(_sb + 1 * PLANE,      pAl + _k0);                                \
        cp16(_sb + 1 * PLANE + 64, pAl + _k0 + 32);                           \
        cp16(_sb + 2 * PLANE,      pBh + _k0);                                \
        cp16(_sb + 2 * PLANE + 64, pBh + _k0 + 32);                           \
        cp16(_sb + 3 * PLANE,      pBl + _k0);                                \
        cp16(_sb + 3 * PLANE + 64, pBl + _k0 + 32);                           \
    } while (0)

    LOAD_STAGE(0, 0); asm volatile("cp.async.commit_group;" ::: "memory");
    LOAD_STAGE(1, 1); asm volatile("cp.async.commit_group;" ::: "memory");

    const uint32_t aoff = ((wm + (lane & 15)) * 72 + ((lane >> 4) << 3)) * 2;
    const uint32_t boff = ((wn + (lane & 7) + ((lane >> 4) << 3)) * 72 + (lane & 8)) * 2;

    int slot = 0, nslot = 2;
    for (int kt = 0; kt < KT; ++kt) {
        asm volatile("cp.async.wait_group 1;" ::: "memory");
        __syncthreads();
        const uint32_t sb = sbase + slot * STAGEB;

        #pragma unroll
        for (int ks = 0; ks < 4; ++ks) {
            const uint32_t kc2 = ks * 32;   // 16 halfs = 32 bytes
            uint32_t ahf[2][4], alf[2][4], bhf[4][2], blf[4][2];
            #pragma unroll
            for (int mt = 0; mt < 2; mt++) {
                ldsm4(ahf[mt], sb + 0 * PLANE + aoff + kc2 + mt * 2304);
                ldsm4(alf[mt], sb + 1 * PLANE + aoff + kc2 + mt * 2304);
            }
            #pragma unroll
            for (int n2 = 0; n2 < 2; n2++) {
                uint32_t r[4];
                ldsm4(r, sb + 2 * PLANE + boff + kc2 + n2 * 2304);
                bhf[n2 * 2][0] = r[0]; bhf[n2 * 2][1] = r[1];
                bhf[n2 * 2 + 1][0] = r[2]; bhf[n2 * 2 + 1][1] = r[3];
                ldsm4(r, sb + 3 * PLANE + boff + kc2 + n2 * 2304);
                blf[n2 * 2][0] = r[0]; blf[n2 * 2][1] = r[1];
                blf[n2 * 2 + 1][0] = r[2]; blf[n2 * 2 + 1][1] = r[3];
            }
            #pragma unroll
            for (int mt = 0; mt < 2; mt++)
                #pragma unroll
                for (int nt = 0; nt < 4; nt++) {
                    mma16816(accm[mt][nt], ahf[mt], bhf[nt]);    // hi*hi (f32)
                    mma16816h(accx[mt][nt], ahf[mt], blf[nt]);   // hi*lo (f16)
                    mma16816h(accx[mt][nt], alf[mt], bhf[nt]);   // lo*hi (f16)
                }
        }
        if (kt + 2 < KT) LOAD_STAGE(kt + 2, nslot);
        asm volatile("cp.async.commit_group;" ::: "memory");
        slot = (slot == 2) ? 0 : slot + 1;
        nslot = (nslot == 2) ? 0 : nslot + 1;
    }

    #pragma unroll
    for (int mt = 0; mt < 2; mt++) {
        const int row = bm + wm + mt * 16 + (lane >> 2);
        float* r0 = C + (size_t)row * ldc + bn + wn + (lane & 3) * 2;
        float* r1 = r0 + (size_t)8 * ldc;
        #pragma unroll
        for (int nt = 0; nt < 4; nt++) {
            const __half2 x01 = *reinterpret_cast<const __half2*>(&accx[mt][nt][0]);
            const __half2 x23 = *reinterpret_cast<const __half2*>(&accx[mt][nt][1]);
            *(float2*)(r0 + nt * 8) = make_float2(
                accm[mt][nt][0] + __low2float(x01),
                accm[mt][nt][1] + __high2float(x01));
            *(float2*)(r1 + nt * 8) = make_float2(
                accm[mt][nt][2] + __low2float(x23),
                accm[mt][nt][3] + __high2float(x23));
        }
    }
#undef LOAD_STAGE
}

// ---------------------------------------------------------------------------
// GEMM2: single-fp16 NT GEMM (1 term, f32 acc), 512 threads, warp tile 32x32.
// CTA 128x128, BK=64, 3-stage, one barrier per kt.
// Stage 36864 B: A@0 | B@18432.
// ---------------------------------------------------------------------------
#define STAGEB1 (2 * PLANE)     // 36864
#define GSMEM1  (3 * STAGEB1)   // 110592

__global__ __launch_bounds__(512, 1) void gemm_h16(
    const __half* __restrict__ A, const __half* __restrict__ B,
    float* __restrict__ C, int lda, int ldb, int ldc, int KT)
{
    extern __shared__ __align__(16) char smem[];
    const uint32_t sbase = smem_u32_of(smem);
    const int tid  = threadIdx.x;
    const int lane = tid & 31;
    const int wid  = tid >> 5;
    const int wm   = (wid >> 2) * 32;
    const int wn   = (wid & 3) * 32;
    const int bm   = blockIdx.y * 128;
    const int bn   = blockIdx.x * 128;

    const int lr = tid >> 2;
    const int lc = tid & 3;
    const __half* pA = A + (size_t)(bm + lr) * lda + lc * 8;
    const __half* pB = B + (size_t)(bn + lr) * ldb + lc * 8;
    const uint32_t so = lr * PITCH + lc * 16;

    float acc[2][4][4];
    #pragma unroll
    for (int i = 0; i < 2; i++)
        #pragma unroll
        for (int j = 0; j < 4; j++)
            #pragma unroll
            for (int k = 0; k < 4; k++) acc[i][j][k] = 0.f;

#define LOAD_S1(kt, slot)                                                     \
    do {                                                                      \
        const int _k0 = (kt) * 64;                                            \
        const uint32_t _sb = sbase + (slot) * STAGEB1 + so;                   \
        cp16(_sb + 0,          pA + _k0);                                     \
        cp16(_sb + 64,         pA + _k0 + 32);                                \
        cp16(_sb + PLANE,      pB + _k0);                                     \
        cp16(_sb + PLANE + 64, pB + _k0 + 32);                                \
    } while (0)

    LOAD_S1(0, 0); asm volatile("cp.async.commit_group;" ::: "memory");
    LOAD_S1(1, 1); asm volatile("cp.async.commit_group;" ::: "memory");

    const uint32_t aoff = ((wm + (lane & 15)) * 72 + ((lane >> 4) << 3)) * 2;
    const uint32_t boff = ((wn + (lane & 7) + ((lane >> 4) << 3)) * 72 + (lane & 8)) * 2;

    int slot = 0, nslot = 2;
    for (int kt = 0; kt < KT; ++kt) {
        asm volatile("cp.async.wait_group 1;" ::: "memory");
        __syncthreads();
        const uint32_t sb = sbase + slot * STAGEB1;

        #pragma unroll
        for (int ks = 0; ks < 4; ++ks) {
            const uint32_t kc2 = ks * 32;
            uint32_t af[2][4], bf[4][2];
            #pragma unroll
            for (int mt = 0; mt < 2; mt++)
                ldsm4(af[mt], sb + aoff + kc2 + mt * 2304);
            #pragma unroll
            for (int n2 = 0; n2 < 2; n2++) {
                uint32_t r[4];
                ldsm4(r, sb + PLANE + boff + kc2 + n2 * 2304);
                bf[n2 * 2][0] = r[0]; bf[n2 * 2][1] = r[1];
                bf[n2 * 2 + 1][0] = r[2]; bf[n2 * 2 + 1][1] = r[3];
            }
            #pragma unroll
            for (int mt = 0; mt < 2; mt++)
                #pragma unroll
                for (int nt = 0; nt < 4; nt++)
                    mma16816(acc[mt][nt], af[mt], bf[nt]);
        }
        if (kt + 2 < KT) LOAD_S1(kt + 2, nslot);
        asm volatile("cp.async.commit_group;" ::: "memory");
        slot = (slot == 2) ? 0 : slot + 1;
        nslot = (nslot == 2) ? 0 : nslot + 1;
    }

    #pragma unroll
    for (int mt = 0; mt < 2; mt++) {
        const int row = bm + wm + mt * 16 + (lane >> 2);
        float* r0 = C + (size_t)row * ldc + bn + wn + (lane & 3) * 2;
        float* r1 = r0 + (size_t)8 * ldc;
        #pragma unroll
        for (int nt = 0; nt < 4; nt++) {
            *(float2*)(r0 + nt * 8) = make_float2(acc[mt][nt][0], acc[mt][nt][1]);
            *(float2*)(r1 + nt * 8) = make_float2(acc[mt][nt][2], acc[mt][nt][3]);
        }
    }
#undef LOAD_S1
}

// ---------------------------------------------------------------------------
// Launch
// ---------------------------------------------------------------------------
extern "C" void kernel_launch(void* const* d_in, const int* in_sizes, int n_in,
                              void* d_out, int out_size)
{
    const float* x = (const float*)d_in[0];   // [16384, 1024]
    const float* w = (const float*)d_in[1];   // [4096, 1024]
    float* out = (float*)d_out;               // [16384, 1024]

    float *scores;
    __half *xhi, *xlo, *whi, *wlo, *wthi, *phi;
    cudaGetSymbolAddress((void**)&scores, g_scores);
    cudaGetSymbolAddress((void**)&xhi, g_xhi);
    cudaGetSymbolAddress((void**)&xlo, g_xlo);
    cudaGetSymbolAddress((void**)&whi, g_whi);
    cudaGetSymbolAddress((void**)&wlo, g_wlo);
    cudaGetSymbolAddress((void**)&wthi, g_wthi);
    cudaGetSymbolAddress((void**)&phi, g_phi);

    cudaFuncSetAttribute(gemm_hsplit, cudaFuncAttributeMaxDynamicSharedMemorySize,
                         GSMEM);
    cudaFuncSetAttribute(gemm_h16, cudaFuncAttributeMaxDynamicSharedMemorySize,
                         GSMEM1);

    // Prep: fused rmsnorm + fp16 hi/lo splits; W transpose (fp16)
    rms_split_kernel<<<MROWS, 256>>>(x, xhi, xlo);
    rms_split_kernel<<<DF,    256>>>(w, whi, wlo);
    {
        dim3 g(DM / 32, DF / 32), b(32, 32);
        wt_kernel<<<g, b>>>(w, wthi);
    }

    // GEMM1 (hi*hi f32 acc + cross f16 acc): scores
    {
        dim3 g(DF / 128, MROWS / 128);   // 32 x 128
        gemm_hsplit<<<g, 512, GSMEM>>>(xhi, xlo, whi, wlo, scores,
                                       DM, DM, DF, DM / 64);
    }

    // softmax rows -> fp16 probs
    softmax_h<<<MROWS, 256>>>(scores, phi);

    // GEMM2 (1-term fp16, f32 acc)
    {
        dim3 g(DM / 128, MROWS / 128);   // 8 x 128
        gemm_h16<<<g, 512, GSMEM1>>>(phi, wthi, out, DF, DF, DM, DF / 64);
    }
}

// round 12
// speedup vs baseline: 1.0168x; 1.0168x over previous
#include <cuda_runtime.h>
#include <cuda_fp16.h>
#include <cstdint>
#include <math_constants.h>

// Problem dims (fixed per reference)
#define DM   1024      // d_model
#define DF   4096      // d_ff
#define MROWS 16384    // 4 * 4096

// ---------------------------------------------------------------------------
// Scratch (allocation-free: __device__ globals)
// ---------------------------------------------------------------------------
__device__ float  g_scores[(size_t)MROWS * DF];   // 256 MB fp32 logits
__device__ __half g_phi[(size_t)MROWS * DF];      // probs (single fp16)
__device__ __half g_xhi[(size_t)MROWS * DM];      // rmsnorm(x) hi
__device__ __half g_xlo[(size_t)MROWS * DM];      // rmsnorm(x) lo
__device__ __half g_whi[(size_t)DF * DM];         // rmsnorm(w) hi
__device__ __half g_wlo[(size_t)DF * DM];         // rmsnorm(w) lo
__device__ __half g_wthi[(size_t)DM * DF];        // W^T (raw w) [d][c]

// ---------------------------------------------------------------------------
// PTX helpers
// ---------------------------------------------------------------------------
__device__ __forceinline__ uint32_t smem_u32_of(const void* p) {
    uint32_t a;
    asm("{ .reg .u64 t; cvta.to.shared.u64 t, %1; cvt.u32.u64 %0, t; }" : "=r"(a) : "l"(p));
    return a;
}

__device__ __forceinline__ void cp16(uint32_t s, const void* g) {
    asm volatile("cp.async.cg.shared.global [%0], [%1], 16;" :: "r"(s), "l"(g));
}

__device__ __forceinline__ void ldsm4(uint32_t* r, uint32_t a) {
    asm volatile("ldmatrix.sync.aligned.m8n8.x4.shared.b16 {%0,%1,%2,%3}, [%4];"
                 : "=r"(r[0]), "=r"(r[1]), "=r"(r[2]), "=r"(r[3]) : "r"(a));
}

__device__ __forceinline__ void mma16816(float* d, const uint32_t* a, const uint32_t* b) {
    asm volatile(
        "mma.sync.aligned.m16n8k16.row.col.f32.f16.f16.f32 "
        "{%0,%1,%2,%3}, {%4,%5,%6,%7}, {%8,%9}, {%0,%1,%2,%3};"
        : "+f"(d[0]), "+f"(d[1]), "+f"(d[2]), "+f"(d[3])
        : "r"(a[0]), "r"(a[1]), "r"(a[2]), "r"(a[3]), "r"(b[0]), "r"(b[1]));
}

// f16-accumulator variant (2-reg D fragment; same thread/element mapping)
__device__ __forceinline__ void mma16816h(uint32_t* d, const uint32_t* a, const uint32_t* b) {
    asm volatile(
        "mma.sync.aligned.m16n8k16.row.col.f16.f16.f16.f16 "
        "{%0,%1}, {%2,%3,%4,%5}, {%6,%7}, {%0,%1};"
        : "+r"(d[0]), "+r"(d[1])
        : "r"(a[0]), "r"(a[1]), "r"(a[2]), "r"(a[3]), "r"(b[0]), "r"(b[1]));
}

// ---------------------------------------------------------------------------
// Kernel: fused per-row rmsnorm + fp16 hi/lo split.
// ---------------------------------------------------------------------------
__device__ __forceinline__ void split2h(float v, __half& h, __half& l) {
    h = __float2half_rn(v);
    l = __float2half_rn(v - __half2float(h));
}

__global__ __launch_bounds__(256) void rms_split_kernel(
    const float* __restrict__ src,
    __half* __restrict__ hi, __half* __restrict__ lo)
{
    const int row = blockIdx.x;
    const int tid = threadIdx.x;
    const size_t base = (size_t)row * DM;

    float4 v = *(const float4*)(src + base + tid * 4);
    float ss = v.x * v.x + v.y * v.y + v.z * v.z + v.w * v.w;

    __shared__ float red[256];
    red[tid] = ss;
    __syncthreads();
    #pragma unroll
    for (int off = 128; off > 0; off >>= 1) {
        if (tid < off) red[tid] += red[tid + off];
        __syncthreads();
    }
    const float s = rsqrtf(red[0] * (1.0f / DM) + 1e-6f);

    __half h0, h1, h2, h3, l0, l1, l2, l3;
    split2h(v.x * s, h0, l0); split2h(v.y * s, h1, l1);
    split2h(v.z * s, h2, l2); split2h(v.w * s, h3, l3);
    __half2* H = (__half2*)(hi + base + tid * 4);
    __half2* L = (__half2*)(lo + base + tid * 4);
    H[0] = __halves2half2(h0, h1); H[1] = __halves2half2(h2, h3);
    L[0] = __halves2half2(l0, l1); L[1] = __halves2half2(l2, l3);
}

// ---------------------------------------------------------------------------
// Kernel: transpose  W[c,d] -> Wt[d,c]  (raw w, single fp16)
// ---------------------------------------------------------------------------
__global__ void wt_kernel(const float* __restrict__ w, __half* __restrict__ th)
{
    __shared__ float t[32][33];
    const int c = blockIdx.y * 32 + threadIdx.y;
    const int d = blockIdx.x * 32 + threadIdx.x;
    t[threadIdx.y][threadIdx.x] = w[(size_t)c * DM + d];
    __syncthreads();
    const int dd = blockIdx.x * 32 + threadIdx.y;
    const int cc = blockIdx.y * 32 + threadIdx.x;
    th[(size_t)dd * DF + cc] = __float2half_rn(t[threadIdx.x][threadIdx.y]);
}

// ---------------------------------------------------------------------------
// Kernel: row softmax over 4096, emits single fp16 probs
// ---------------------------------------------------------------------------
__global__ __launch_bounds__(256) void softmax_h(const float* __restrict__ S,
                                                 __half* __restrict__ PH)
{
    const int row = blockIdx.x;
    const int tid = threadIdx.x;
    const float* p = S + (size_t)row * DF + tid * 16;

    float v[16];
    #pragma unroll
    for (int j = 0; j < 4; j++) {
        float4 t = *(const float4*)(p + j * 4);
        v[j * 4 + 0] = t.x; v[j * 4 + 1] = t.y;
        v[j * 4 + 2] = t.z; v[j * 4 + 3] = t.w;
    }
    float lm = v[0];
    #pragma unroll
    for (int j = 1; j < 16; j++) lm = fmaxf(lm, v[j]);

    __shared__ float red[256];
    red[tid] = lm;
    __syncthreads();
    #pragma unroll
    for (int off = 128; off > 0; off >>= 1) {
        if (tid < off) red[tid] = fmaxf(red[tid], red[tid + off]);
        __syncthreads();
    }
    const float m = red[0];
    __syncthreads();

    float ls = 0.f;
    #pragma unroll
    for (int j = 0; j < 16; j++) {
        v[j] = __expf(v[j] - m);
        ls += v[j];
    }
    red[tid] = ls;
    __syncthreads();
    #pragma unroll
    for (int off = 128; off > 0; off >>= 1) {
        if (tid < off) red[tid] += red[tid + off];
        __syncthreads();
    }
    const float inv = 1.0f / red[0];

    __half2* ph2 = (__half2*)(PH + (size_t)row * DF + tid * 16);
    #pragma unroll
    for (int j = 0; j < 8; j++) {
        ph2[j] = __halves2half2(__float2half_rn(v[2 * j] * inv),
                                __float2half_rn(v[2 * j + 1] * inv));
    }
}

// ---------------------------------------------------------------------------
// GEMM1: split-fp16 NT GEMM, 256 threads / 8 warps, warp grid 4x2 (tile 32x32).
//   main  : Ah*Bh  f32 acc;  cross: Ah*Bl + Al*Bh shared f16 acc.
// CTA 128x64, BK=32, 3-stage cp.async ring -> 92 KB smem => 2 CTAs per SM.
// Independent co-resident CTAs hide each other's barrier/LDSM stalls.
// Stage 30720 B: Ah(128x80)@0 | Al@10240 | Bh(64x80)@20480 | Bl@25600.
// ---------------------------------------------------------------------------
#define APL  10240                   // A plane bytes (128 x 80)
#define BPL  5120                    // B plane bytes (64 x 80)
#define STG  (2 * APL + 2 * BPL)     // 30720
#define GSMEM (3 * STG)              // 92160

__global__ __launch_bounds__(256, 2) void gemm_hsplit(
    const __half* __restrict__ Ah, const __half* __restrict__ Al,
    const __half* __restrict__ Bh, const __half* __restrict__ Bl,
    float* __restrict__ C, int lda, int ldb, int ldc, int KT)
{
    extern __shared__ __align__(16) char smem[];
    const uint32_t sbase = smem_u32_of(smem);
    const int tid  = threadIdx.x;
    const int lane = tid & 31;
    const int wid  = tid >> 5;           // 0..7
    const int wm   = (wid >> 1) * 32;    // 0,32,64,96
    const int wn   = (wid & 1) * 32;     // 0,32
    const int bm   = blockIdx.y * 128;
    const int bn   = blockIdx.x * 64;

    // loader: 256 threads; A planes rows lr & lr+64 (2 chunks), B planes row lr.
    const int lr = tid >> 2;             // 0..63
    const int lc = tid & 3;              // 16B chunk
    const __half* pAh = Ah + (size_t)(bm + lr) * lda + lc * 8;
    const __half* pAl = Al + (size_t)(bm + lr) * lda + lc * 8;
    const __half* pBh = Bh + (size_t)(bn + lr) * ldb + lc * 8;
    const __half* pBl = Bl + (size_t)(bn + lr) * ldb + lc * 8;
    const size_t rstepA = (size_t)64 * lda;
    const uint32_t so = lr * 80 + lc * 16;

    float    accm[2][4][4];   // hi*hi, f32 acc
    uint32_t accx[2][4][2];   // cross, f16 acc
    #pragma unroll
    for (int i = 0; i < 2; i++)
        #pragma unroll
        for (int j = 0; j < 4; j++) {
            #pragma unroll
            for (int k = 0; k < 4; k++) accm[i][j][k] = 0.f;
            accx[i][j][0] = 0u; accx[i][j][1] = 0u;
        }

#define LOAD_STAGE(kt, slot)                                                  \
    do {                                                                      \
        const int _k0 = (kt) * 32;                                            \
        const uint32_t _sb = sbase + (slot) * STG + so;                       \
        cp16(_sb + 0,           pAh + _k0);                                   \
        cp16(_sb + 5120,        pAh + _k0 + rstepA);                          \
        cp16(_sb + APL,         pAl + _k0);                                   \
        cp16(_sb + APL + 5120,  pAl + _k0 + rstepA);                          \
        cp16(_sb + 2 * APL,       pBh + _k0);                                 \
        cp16(_sb + 2 * APL + BPL, pBl + _k0);                                 \
    } while (0)

    LOAD_STAGE(0, 0); asm volatile("cp.async.commit_group;" ::: "memory");
    LOAD_STAGE(1, 1); asm volatile("cp.async.commit_group;" ::: "memory");

    const uint32_t aoff = ((wm + (lane & 15)) * 40 + ((lane >> 4) << 3)) * 2;
    const uint32_t boff = ((wn + (lane & 7) + ((lane >> 4) << 3)) * 40 + (lane & 8)) * 2;

    int slot = 0, nslot = 2;
    for (int kt = 0; kt < KT; ++kt) {
        asm volatile("cp.async.wait_group 1;" ::: "memory");
        __syncthreads();
        const uint32_t sb = sbase + slot * STG;

        #pragma unroll
        for (int ks = 0; ks < 2; ++ks) {
            const uint32_t kc2 = ks * 32;
            uint32_t ahf[2][4], alf[2][4], bhf[4][2], blf[4][2];
            #pragma unroll
            for (int mt = 0; mt < 2; mt++) {
                ldsm4(ahf[mt], sb + aoff + kc2 + mt * 1280);
                ldsm4(alf[mt], sb + APL + aoff + kc2 + mt * 1280);
            }
            #pragma unroll
            for (int n2 = 0; n2 < 2; n2++) {
                uint32_t r[4];
                ldsm4(r, sb + 2 * APL + boff + kc2 + n2 * 1280);
                bhf[n2 * 2][0] = r[0]; bhf[n2 * 2][1] = r[1];
                bhf[n2 * 2 + 1][0] = r[2]; bhf[n2 * 2 + 1][1] = r[3];
                ldsm4(r, sb + 2 * APL + BPL + boff + kc2 + n2 * 1280);
                blf[n2 * 2][0] = r[0]; blf[n2 * 2][1] = r[1];
                blf[n2 * 2 + 1][0] = r[2]; blf[n2 * 2 + 1][1] = r[3];
            }
            #pragma unroll
            for (int mt = 0; mt < 2; mt++)
                #pragma unroll
                for (int nt = 0; nt < 4; nt++) {
                    mma16816(accm[mt][nt], ahf[mt], bhf[nt]);    // hi*hi (f32)
                    mma16816h(accx[mt][nt], ahf[mt], blf[nt]);   // hi*lo (f16)
                    mma16816h(accx[mt][nt], alf[mt], bhf[nt]);   // lo*hi (f16)
                }
        }
        if (kt + 2 < KT) LOAD_STAGE(kt + 2, nslot);
        asm volatile("cp.async.commit_group;" ::: "memory");
        slot = (slot == 2) ? 0 : slot + 1;
        nslot = (nslot == 2) ? 0 : nslot + 1;
    }

    #pragma unroll
    for (int mt = 0; mt < 2; mt++) {
        const int row = bm + wm + mt * 16 + (lane >> 2);
        float* r0 = C + (size_t)row * ldc + bn + wn + (lane & 3) * 2;
        float* r1 = r0 + (size_t)8 * ldc;
        #pragma unroll
        for (int nt = 0; nt < 4; nt++) {
            const __half2 x01 = *reinterpret_cast<const __half2*>(&accx[mt][nt][0]);
            const __half2 x23 = *reinterpret_cast<const __half2*>(&accx[mt][nt][1]);
            *(float2*)(r0 + nt * 8) = make_float2(
                accm[mt][nt][0] + __low2float(x01),
                accm[mt][nt][1] + __high2float(x01));
            *(float2*)(r1 + nt * 8) = make_float2(
                accm[mt][nt][2] + __low2float(x23),
                accm[mt][nt][3] + __high2float(x23));
        }
    }
#undef LOAD_STAGE
}

// ---------------------------------------------------------------------------
// GEMM2: single-fp16 NT GEMM (1 term, f32 acc), 256 threads, CTA 128x64.
// BK=32, 4-stage ring -> 61 KB smem => 2+ CTAs per SM.
// Stage 15360 B: A(128x80)@0 | B(64x80)@10240.
// ---------------------------------------------------------------------------
#define STG1   (APL + BPL)       // 15360
#define GSMEM1 (4 * STG1)        // 61440

__global__ __launch_bounds__(256, 2) void gemm_h16(
    const __half* __restrict__ A, const __half* __restrict__ B,
    float* __restrict__ C, int lda, int ldb, int ldc, int KT)
{
    extern __shared__ __align__(16) char smem[];
    const uint32_t sbase = smem_u32_of(smem);
    const int tid  = threadIdx.x;
    const int lane = tid & 31;
    const int wid  = tid >> 5;
    const int wm   = (wid >> 1) * 32;
    const int wn   = (wid & 1) * 32;
    const int bm   = blockIdx.y * 128;
    const int bn   = blockIdx.x * 64;

    const int lr = tid >> 2;
    const int lc = tid & 3;
    const __half* pA = A + (size_t)(bm + lr) * lda + lc * 8;
    const __half* pB = B + (size_t)(bn + lr) * ldb + lc * 8;
    const size_t rstepA = (size_t)64 * lda;
    const uint32_t so = lr * 80 + lc * 16;

    float acc[2][4][4];
    #pragma unroll
    for (int i = 0; i < 2; i++)
        #pragma unroll
        for (int j = 0; j < 4; j++)
            #pragma unroll
            for (int k = 0; k < 4; k++) acc[i][j][k] = 0.f;

#define LOAD_S1(kt)                                                           \
    do {                                                                      \
        const int _k0 = (kt) * 32;                                            \
        const uint32_t _sb = sbase + ((kt) & 3) * STG1 + so;                  \
        cp16(_sb + 0,    pA + _k0);                                           \
        cp16(_sb + 5120, pA + _k0 + rstepA);                                  \
        cp16(_sb + APL,  pB + _k0);                                           \
    } while (0)

    LOAD_S1(0); asm volatile("cp.async.commit_group;" ::: "memory");
    LOAD_S1(1); asm volatile("cp.async.commit_group;" ::: "memory");
    LOAD_S1(2); asm volatile("cp.async.commit_group;" ::: "memory");

    const uint32_t aoff = ((wm + (lane & 15)) * 40 + ((lane >> 4) << 3)) * 2;
    const uint32_t boff = ((wn + (lane & 7) + ((lane >> 4) << 3)) * 40 + (lane & 8)) * 2;

    for (int kt = 0; kt < KT; ++kt) {
        asm volatile("cp.async.wait_group 2;" ::: "memory");
        __syncthreads();
        const uint32_t sb = sbase + (kt & 3) * STG1;

        #pragma unroll
        for (int ks = 0; ks < 2; ++ks) {
            const uint32_t kc2 = ks * 32;
            uint32_t af[2][4], bf[4][2];
            #pragma unroll
            for (int mt = 0; mt < 2; mt++)
                ldsm4(af[mt], sb + aoff + kc2 + mt * 1280);
            #pragma unroll
            for (int n2 = 0; n2 < 2; n2++) {
                uint32_t r[4];
                ldsm4(r, sb + APL + boff + kc2 + n2 * 1280);
                bf[n2 * 2][0] = r[0]; bf[n2 * 2][1] = r[1];
                bf[n2 * 2 + 1][0] = r[2]; bf[n2 * 2 + 1][1] = r[3];
            }
            #pragma unroll
            for (int mt = 0; mt < 2; mt++)
                #pragma unroll
                for (int nt = 0; nt < 4; nt++)
                    mma16816(acc[mt][nt], af[mt], bf[nt]);
        }
        __syncthreads();
        if (kt + 3 < KT) LOAD_S1(kt + 3);
        asm volatile("cp.async.commit_group;" ::: "memory");
    }

    #pragma unroll
    for (int mt = 0; mt < 2; mt++) {
        const int row = bm + wm + mt * 16 + (lane >> 2);
        float* r0 = C + (size_t)row * ldc + bn + wn + (lane & 3) * 2;
        float* r1 = r0 + (size_t)8 * ldc;
        #pragma unroll
        for (int nt = 0; nt < 4; nt++) {
            *(float2*)(r0 + nt * 8) = make_float2(acc[mt][nt][0], acc[mt][nt][1]);
            *(float2*)(r1 + nt * 8) = make_float2(acc[mt][nt][2], acc[mt][nt][3]);
        }
    }
#undef LOAD_S1
}

// ---------------------------------------------------------------------------
// Launch
// ---------------------------------------------------------------------------
extern "C" void kernel_launch(void* const* d_in, const int* in_sizes, int n_in,
                              void* d_out, int out_size)
{
    const float* x = (const float*)d_in[0];   // [16384, 1024]
    const float* w = (const float*)d_in[1];   // [4096, 1024]
    float* out = (float*)d_out;               // [16384, 1024]

    float *scores;
    __half *xhi, *xlo, *whi, *wlo, *wthi, *phi;
    cudaGetSymbolAddress((void**)&scores, g_scores);
    cudaGetSymbolAddress((void**)&xhi, g_xhi);
    cudaGetSymbolAddress((void**)&xlo, g_xlo);
    cudaGetSymbolAddress((void**)&whi, g_whi);
    cudaGetSymbolAddress((void**)&wlo, g_wlo);
    cudaGetSymbolAddress((void**)&wthi, g_wthi);
    cudaGetSymbolAddress((void**)&phi, g_phi);

    cudaFuncSetAttribute(gemm_hsplit, cudaFuncAttributeMaxDynamicSharedMemorySize,
                         GSMEM);
    cudaFuncSetAttribute(gemm_h16, cudaFuncAttributeMaxDynamicSharedMemorySize,
                         GSMEM1);

    // Prep: fused rmsnorm + fp16 hi/lo splits; W transpose (fp16)
    rms_split_kernel<<<MROWS, 256>>>(x, xhi, xlo);
    rms_split_kernel<<<DF,    256>>>(w, whi, wlo);
    {
        dim3 g(DM / 32, DF / 32), b(32, 32);
        wt_kernel<<<g, b>>>(w, wthi);
    }

    // GEMM1 (hi*hi f32 acc + cross f16 acc): scores
    {
        dim3 g(DF / 64, MROWS / 128);    // 64 x 128
        gemm_hsplit<<<g, 256, GSMEM>>>(xhi, xlo, whi, wlo, scores,
                                       DM, DM, DF, DM / 32);
    }

    // softmax rows -> fp16 probs
    softmax_h<<<MROWS, 256>>>(scores, phi);

    // GEMM2 (1-term fp16, f32 acc)
    {
        dim3 g(DM / 64, MROWS / 128);    // 16 x 128
        gemm_h16<<<g, 256, GSMEM1>>>(phi, wthi, out, DF, DF, DM, DF / 32);
    }
}

// round 14
// speedup vs baseline: 1.0173x; 1.0005x over previous
#include <cuda_runtime.h>
#include <cuda_fp16.h>
#include <cstdint>
#include <math_constants.h>

// Problem dims (fixed per reference)
#define DM   1024      // d_model
#define DF   4096      // d_ff
#define MROWS 16384    // 4 * 4096

// ---------------------------------------------------------------------------
// Scratch (allocation-free: __device__ globals)
// ---------------------------------------------------------------------------
__device__ float  g_scores[(size_t)MROWS * DF];   // 256 MB fp32 logits
__device__ __half g_phi[(size_t)MROWS * DF];      // probs (single fp16)
__device__ __half g_xhi[(size_t)MROWS * DM];      // rmsnorm(x) hi
__device__ __half g_xlo[(size_t)MROWS * DM];      // rmsnorm(x) lo
__device__ __half g_whi[(size_t)DF * DM];         // rmsnorm(w) hi
__device__ __half g_wlo[(size_t)DF * DM];         // rmsnorm(w) lo
__device__ __half g_wthi[(size_t)DM * DF];        // W^T (raw w) [d][c]

// ---------------------------------------------------------------------------
// PTX helpers
// ---------------------------------------------------------------------------
__device__ __forceinline__ uint32_t smem_u32_of(const void* p) {
    uint32_t a;
    asm("{ .reg .u64 t; cvta.to.shared.u64 t, %1; cvt.u32.u64 %0, t; }" : "=r"(a) : "l"(p));
    return a;
}

__device__ __forceinline__ void cp16(uint32_t s, const void* g) {
    asm volatile("cp.async.cg.shared.global [%0], [%1], 16;" :: "r"(s), "l"(g));
}

__device__ __forceinline__ void ldsm4(uint32_t* r, uint32_t a) {
    asm volatile("ldmatrix.sync.aligned.m8n8.x4.shared.b16 {%0,%1,%2,%3}, [%4];"
                 : "=r"(r[0]), "=r"(r[1]), "=r"(r[2]), "=r"(r[3]) : "r"(a));
}

__device__ __forceinline__ void mma16816(float* d, const uint32_t* a, const uint32_t* b) {
    asm volatile(
        "mma.sync.aligned.m16n8k16.row.col.f32.f16.f16.f32 "
        "{%0,%1,%2,%3}, {%4,%5,%6,%7}, {%8,%9}, {%0,%1,%2,%3};"
        : "+f"(d[0]), "+f"(d[1]), "+f"(d[2]), "+f"(d[3])
        : "r"(a[0]), "r"(a[1]), "r"(a[2]), "r"(a[3]), "r"(b[0]), "r"(b[1]));
}

// f16-accumulator variant (2-reg D fragment; same thread/element mapping)
__device__ __forceinline__ void mma16816h(uint32_t* d, const uint32_t* a, const uint32_t* b) {
    asm volatile(
        "mma.sync.aligned.m16n8k16.row.col.f16.f16.f16.f16 "
        "{%0,%1}, {%2,%3,%4,%5}, {%6,%7}, {%0,%1};"
        : "+r"(d[0]), "+r"(d[1])
        : "r"(a[0]), "r"(a[1]), "r"(a[2]), "r"(a[3]), "r"(b[0]), "r"(b[1]));
}

// ---------------------------------------------------------------------------
// Kernel: fused per-row rmsnorm + fp16 hi/lo split for BOTH x and w.
// Blocks [0, MROWS) -> x rows; blocks [MROWS, MROWS+DF) -> w rows.
// ---------------------------------------------------------------------------
__device__ __forceinline__ void split2h(float v, __half& h, __half& l) {
    h = __float2half_rn(v);
    l = __float2half_rn(v - __half2float(h));
}

__global__ __launch_bounds__(256) void rms_split_all(
    const float* __restrict__ x, const float* __restrict__ w,
    __half* __restrict__ xhi, __half* __restrict__ xlo,
    __half* __restrict__ whi, __half* __restrict__ wlo)
{
    const int blk = blockIdx.x;
    const bool isW = blk >= MROWS;
    const int row = isW ? (blk - MROWS) : blk;
    const float* src = isW ? w : x;
    __half* hi = isW ? whi : xhi;
    __half* lo = isW ? wlo : xlo;

    const int tid = threadIdx.x;
    const size_t base = (size_t)row * DM;

    float4 v = *(const float4*)(src + base + tid * 4);
    float ss = v.x * v.x + v.y * v.y + v.z * v.z + v.w * v.w;

    __shared__ float red[256];
    red[tid] = ss;
    __syncthreads();
    #pragma unroll
    for (int off = 128; off > 0; off >>= 1) {
        if (tid < off) red[tid] += red[tid + off];
        __syncthreads();
    }
    const float s = rsqrtf(red[0] * (1.0f / DM) + 1e-6f);

    __half h0, h1, h2, h3, l0, l1, l2, l3;
    split2h(v.x * s, h0, l0); split2h(v.y * s, h1, l1);
    split2h(v.z * s, h2, l2); split2h(v.w * s, h3, l3);
    __half2* H = (__half2*)(hi + base + tid * 4);
    __half2* L = (__half2*)(lo + base + tid * 4);
    H[0] = __halves2half2(h0, h1); H[1] = __halves2half2(h2, h3);
    L[0] = __halves2half2(l0, l1); L[1] = __halves2half2(l2, l3);
}

// ---------------------------------------------------------------------------
// Kernel: transpose  W[c,d] -> Wt[d,c]  (raw w, single fp16)
// ---------------------------------------------------------------------------
__global__ void wt_kernel(const float* __restrict__ w, __half* __restrict__ th)
{
    __shared__ float t[32][33];
    const int c = blockIdx.y * 32 + threadIdx.y;
    const int d = blockIdx.x * 32 + threadIdx.x;
    t[threadIdx.y][threadIdx.x] = w[(size_t)c * DM + d];
    __syncthreads();
    const int dd = blockIdx.x * 32 + threadIdx.y;
    const int cc = blockIdx.y * 32 + threadIdx.x;
    th[(size_t)dd * DF + cc] = __float2half_rn(t[threadIdx.x][threadIdx.y]);
}

// ---------------------------------------------------------------------------
// Kernel: row softmax over 4096, emits single fp16 probs
// ---------------------------------------------------------------------------
__global__ __launch_bounds__(256) void softmax_h(const float* __restrict__ S,
                                                 __half* __restrict__ PH)
{
    const int row = blockIdx.x;
    const int tid = threadIdx.x;
    const float* p = S + (size_t)row * DF + tid * 16;

    float v[16];
    #pragma unroll
    for (int j = 0; j < 4; j++) {
        float4 t = *(const float4*)(p + j * 4);
        v[j * 4 + 0] = t.x; v[j * 4 + 1] = t.y;
        v[j * 4 + 2] = t.z; v[j * 4 + 3] = t.w;
    }
    float lm = v[0];
    #pragma unroll
    for (int j = 1; j < 16; j++) lm = fmaxf(lm, v[j]);

    __shared__ float red[256];
    red[tid] = lm;
    __syncthreads();
    #pragma unroll
    for (int off = 128; off > 0; off >>= 1) {
        if (tid < off) red[tid] = fmaxf(red[tid], red[tid + off]);
        __syncthreads();
    }
    const float m = red[0];
    __syncthreads();

    float ls = 0.f;
    #pragma unroll
    for (int j = 0; j < 16; j++) {
        v[j] = __expf(v[j] - m);
        ls += v[j];
    }
    red[tid] = ls;
    __syncthreads();
    #pragma unroll
    for (int off = 128; off > 0; off >>= 1) {
        if (tid < off) red[tid] += red[tid + off];
        __syncthreads();
    }
    const float inv = 1.0f / red[0];

    __half2* ph2 = (__half2*)(PH + (size_t)row * DF + tid * 16);
    #pragma unroll
    for (int j = 0; j < 8; j++) {
        ph2[j] = __halves2half2(__float2half_rn(v[2 * j] * inv),
                                __float2half_rn(v[2 * j + 1] * inv));
    }
}

// ---------------------------------------------------------------------------
// GEMM1: split-fp16 NT GEMM, 256 threads / 8 warps, warp grid 4x2 (tile 32x32).
//   main  : Ah*Bh  f32 acc;  cross: Ah*Bl + Al*Bh shared f16 acc.
// CTA 128x64, BK=32, 3-stage cp.async ring -> 92 KB smem => 2 CTAs per SM.
// Stage 30720 B: Ah(128x80)@0 | Al@10240 | Bh(64x80)@20480 | Bl@25600.
// ---------------------------------------------------------------------------
#define APL  10240                   // A plane bytes (128 x 80)
#define BPL  5120                    // B plane bytes (64 x 80)
#define STG  (2 * APL + 2 * BPL)     // 30720
#define GSMEM (3 * STG)              // 92160

__global__ __launch_bounds__(256, 2) void gemm_hsplit(
    const __half* __restrict__ Ah, const __half* __restrict__ Al,
    const __half* __restrict__ Bh, const __half* __restrict__ Bl,
    float* __restrict__ C, int lda, int ldb, int ldc, int KT)
{
    extern __shared__ __align__(16) char smem[];
    const uint32_t sbase = smem_u32_of(smem);
    const int tid  = threadIdx.x;
    const int lane = tid & 31;
    const int wid  = tid >> 5;           // 0..7
    const int wm   = (wid >> 1) * 32;    // 0,32,64,96
    const int wn   = (wid & 1) * 32;     // 0,32
    const int bm   = blockIdx.y * 128;
    const int bn   = blockIdx.x * 64;

    const int lr = tid >> 2;             // 0..63
    const int lc = tid & 3;              // 16B chunk
    const __half* pAh = Ah + (size_t)(bm + lr) * lda + lc * 8;
    const __half* pAl = Al + (size_t)(bm + lr) * lda + lc * 8;
    const __half* pBh = Bh + (size_t)(bn + lr) * ldb + lc * 8;
    const __half* pBl = Bl + (size_t)(bn + lr) * ldb + lc * 8;
    const size_t rstepA = (size_t)64 * lda;
    const uint32_t so = lr * 80 + lc * 16;

    float    accm[2][4][4];   // hi*hi, f32 acc
    uint32_t accx[2][4][2];   // cross, f16 acc
    #pragma unroll
    for (int i = 0; i < 2; i++)
        #pragma unroll
        for (int j = 0; j < 4; j++) {
            #pragma unroll
            for (int k = 0; k < 4; k++) accm[i][j][k] = 0.f;
            accx[i][j][0] = 0u; accx[i][j][1] = 0u;
        }

#define LOAD_STAGE(kt, slot)                                                  \
    do {                                                                      \
        const int _k0 = (kt) * 32;                                            \
        const uint32_t _sb = sbase + (slot) * STG + so;                       \
        cp16(_sb + 0,           pAh + _k0);                                   \
        cp16(_sb + 5120,        pAh + _k0 + rstepA);                          \
        cp16(_sb + APL,         pAl + _k0);                                   \
        cp16(_sb + APL + 5120,  pAl + _k0 + rstepA);                          \
        cp16(_sb + 2 * APL,       pBh + _k0);                                 \
        cp16(_sb + 2 * APL + BPL, pBl + _k0);                                 \
    } while (0)

    LOAD_STAGE(0, 0); asm volatile("cp.async.commit_group;" ::: "memory");
    LOAD_STAGE(1, 1); asm volatile("cp.async.commit_group;" ::: "memory");

    const uint32_t aoff = ((wm + (lane & 15)) * 40 + ((lane >> 4) << 3)) * 2;
    const uint32_t boff = ((wn + (lane & 7) + ((lane >> 4) << 3)) * 40 + (lane & 8)) * 2;

    int slot = 0, nslot = 2;
    for (int kt = 0; kt < KT; ++kt) {
        asm volatile("cp.async.wait_group 1;" ::: "memory");
        __syncthreads();
        const uint32_t sb = sbase + slot * STG;

        #pragma unroll
        for (int ks = 0; ks < 2; ++ks) {
            const uint32_t kc2 = ks * 32;
            uint32_t ahf[2][4], alf[2][4], bhf[4][2], blf[4][2];
            #pragma unroll
            for (int mt = 0; mt < 2; mt++) {
                ldsm4(ahf[mt], sb + aoff + kc2 + mt * 1280);
                ldsm4(alf[mt], sb + APL + aoff + kc2 + mt * 1280);
            }
            #pragma unroll
            for (int n2 = 0; n2 < 2; n2++) {
                uint32_t r[4];
                ldsm4(r, sb + 2 * APL + boff + kc2 + n2 * 1280);
                bhf[n2 * 2][0] = r[0]; bhf[n2 * 2][1] = r[1];
                bhf[n2 * 2 + 1][0] = r[2]; bhf[n2 * 2 + 1][1] = r[3];
                ldsm4(r, sb + 2 * APL + BPL + boff + kc2 + n2 * 1280);
                blf[n2 * 2][0] = r[0]; blf[n2 * 2][1] = r[1];
                blf[n2 * 2 + 1][0] = r[2]; blf[n2 * 2 + 1][1] = r[3];
            }
            #pragma unroll
            for (int mt = 0; mt < 2; mt++)
                #pragma unroll
                for (int nt = 0; nt < 4; nt++) {
                    mma16816(accm[mt][nt], ahf[mt], bhf[nt]);    // hi*hi (f32)
                    mma16816h(accx[mt][nt], ahf[mt], blf[nt]);   // hi*lo (f16)
                    mma16816h(accx[mt][nt], alf[mt], bhf[nt]);   // lo*hi (f16)
                }
        }
        if (kt + 2 < KT) LOAD_STAGE(kt + 2, nslot);
        asm volatile("cp.async.commit_group;" ::: "memory");
        slot = (slot == 2) ? 0 : slot + 1;
        nslot = (nslot == 2) ? 0 : nslot + 1;
    }

    #pragma unroll
    for (int mt = 0; mt < 2; mt++) {
        const int row = bm + wm + mt * 16 + (lane >> 2);
        float* r0 = C + (size_t)row * ldc + bn + wn + (lane & 3) * 2;
        float* r1 = r0 + (size_t)8 * ldc;
        #pragma unroll
        for (int nt = 0; nt < 4; nt++) {
            const __half2 x01 = *reinterpret_cast<const __half2*>(&accx[mt][nt][0]);
            const __half2 x23 = *reinterpret_cast<const __half2*>(&accx[mt][nt][1]);
            *(float2*)(r0 + nt * 8) = make_float2(
                accm[mt][nt][0] + __low2float(x01),
                accm[mt][nt][1] + __high2float(x01));
            *(float2*)(r1 + nt * 8) = make_float2(
                accm[mt][nt][2] + __low2float(x23),
                accm[mt][nt][3] + __high2float(x23));
        }
    }
#undef LOAD_STAGE
}

// ---------------------------------------------------------------------------
// GEMM2: single-fp16 NT GEMM (1 term, f32 acc), 256 threads, CTA 128x64.
// BK=32, 4-stage ring -> 61 KB smem => 2+ CTAs per SM.
// Stage 15360 B: A(128x80)@0 | B(64x80)@10240.
// ---------------------------------------------------------------------------
#define STG1   (APL + BPL)       // 15360
#define GSMEM1 (4 * STG1)        // 61440

__global__ __launch_bounds__(256, 2) void gemm_h16(
    const __half* __restrict__ A, const __half* __restrict__ B,
    float* __restrict__ C, int lda, int ldb, int ldc, int KT)
{
    extern __shared__ __align__(16) char smem[];
    const uint32_t sbase = smem_u32_of(smem);
    const int tid  = threadIdx.x;
    const int lane = tid & 31;
    const int wid  = tid >> 5;
    const int wm   = (wid >> 1) * 32;
    const int wn   = (wid & 1) * 32;
    const int bm   = blockIdx.y * 128;
    const int bn   = blockIdx.x * 64;

    const int lr = tid >> 2;
    const int lc = tid & 3;
    const __half* pA = A + (size_t)(bm + lr) * lda + lc * 8;
    const __half* pB = B + (size_t)(bn + lr) * ldb + lc * 8;
    const size_t rstepA = (size_t)64 * lda;
    const uint32_t so = lr * 80 + lc * 16;

    float acc[2][4][4];
    #pragma unroll
    for (int i = 0; i < 2; i++)
        #pragma unroll
        for (int j = 0; j < 4; j++)
            #pragma unroll
            for (int k = 0; k < 4; k++) acc[i][j][k] = 0.f;

#define LOAD_S1(kt)                                                           \
    do {                                                                      \
        const int _k0 = (kt) * 32;                                            \
        const uint32_t _sb = sbase + ((kt) & 3) * STG1 + so;                  \
        cp16(_sb + 0,    pA + _k0);                                           \
        cp16(_sb + 5120, pA + _k0 + rstepA);                                  \
        cp16(_sb + APL,  pB + _k0);                                           \
    } while (0)

    LOAD_S1(0); asm volatile("cp.async.commit_group;" ::: "memory");
    LOAD_S1(1); asm volatile("cp.async.commit_group;" ::: "memory");
    LOAD_S1(2); asm volatile("cp.async.commit_group;" ::: "memory");

    const uint32_t aoff = ((wm + (lane & 15)) * 40 + ((lane >> 4) << 3)) * 2;
    const uint32_t boff = ((wn + (lane & 7) + ((lane >> 4) << 3)) * 40 + (lane & 8)) * 2;

    for (int kt = 0; kt < KT; ++kt) {
        asm volatile("cp.async.wait_group 2;" ::: "memory");
        __syncthreads();
        const uint32_t sb = sbase + (kt & 3) * STG1;

        #pragma unroll
        for (int ks = 0; ks < 2; ++ks) {
            const uint32_t kc2 = ks * 32;
            uint32_t af[2][4], bf[4][2];
            #pragma unroll
            for (int mt = 0; mt < 2; mt++)
                ldsm4(af[mt], sb + aoff + kc2 + mt * 1280);
            #pragma unroll
            for (int n2 = 0; n2 < 2; n2++) {
                uint32_t r[4];
                ldsm4(r, sb + APL + boff + kc2 + n2 * 1280);
                bf[n2 * 2][0] = r[0]; bf[n2 * 2][1] = r[1];
                bf[n2 * 2 + 1][0] = r[2]; bf[n2 * 2 + 1][1] = r[3];
            }
            #pragma unroll
            for (int mt = 0; mt < 2; mt++)
                #pragma unroll
                for (int nt = 0; nt < 4; nt++)
                    mma16816(acc[mt][nt], af[mt], bf[nt]);
        }
        __syncthreads();
        if (kt + 3 < KT) LOAD_S1(kt + 3);
        asm volatile("cp.async.commit_group;" ::: "memory");
    }

    #pragma unroll
    for (int mt = 0; mt < 2; mt++) {
        const int row = bm + wm + mt * 16 + (lane >> 2);
        float* r0 = C + (size_t)row * ldc + bn + wn + (lane & 3) * 2;
        float* r1 = r0 + (size_t)8 * ldc;
        #pragma unroll
        for (int nt = 0; nt < 4; nt++) {
            *(float2*)(r0 + nt * 8) = make_float2(acc[mt][nt][0], acc[mt][nt][1]);
            *(float2*)(r1 + nt * 8) = make_float2(acc[mt][nt][2], acc[mt][nt][3]);
        }
    }
#undef LOAD_S1
}

// ---------------------------------------------------------------------------
// Launch (single stream; no stream/event objects -> allocation-guard safe)
// ---------------------------------------------------------------------------
extern "C" void kernel_launch(void* const* d_in, const int* in_sizes, int n_in,
                              void* d_out, int out_size)
{
    const float* x = (const float*)d_in[0];   // [16384, 1024]
    const float* w = (const float*)d_in[1];   // [4096, 1024]
    float* out = (float*)d_out;               // [16384, 1024]

    float *scores;
    __half *xhi, *xlo, *whi, *wlo, *wthi, *phi;
    cudaGetSymbolAddress((void**)&scores, g_scores);
    cudaGetSymbolAddress((void**)&xhi, g_xhi);
    cudaGetSymbolAddress((void**)&xlo, g_xlo);
    cudaGetSymbolAddress((void**)&whi, g_whi);
    cudaGetSymbolAddress((void**)&wlo, g_wlo);
    cudaGetSymbolAddress((void**)&wthi, g_wthi);
    cudaGetSymbolAddress((void**)&phi, g_phi);

    cudaFuncSetAttribute(gemm_hsplit, cudaFuncAttributeMaxDynamicSharedMemorySize,
                         GSMEM);
    cudaFuncSetAttribute(gemm_h16, cudaFuncAttributeMaxDynamicSharedMemorySize,
                         GSMEM1);

    // Prep: fused rmsnorm + fp16 hi/lo splits for x AND w in one launch
    rms_split_all<<<MROWS + DF, 256>>>(x, w, xhi, xlo, whi, wlo);
    {
        dim3 g(DM / 32, DF / 32), b(32, 32);
        wt_kernel<<<g, b>>>(w, wthi);
    }

    // GEMM1 (hi*hi f32 acc + cross f16 acc): scores
    {
        dim3 g(DF / 64, MROWS / 128);    // 64 x 128
        gemm_hsplit<<<g, 256, GSMEM>>>(xhi, xlo, whi, wlo, scores,
                                       DM, DM, DF, DM / 32);
    }

    // softmax rows -> fp16 probs
    softmax_h<<<MROWS, 256>>>(scores, phi);

    // GEMM2 (1-term fp16, f32 acc)
    {
        dim3 g(DM / 64, MROWS / 128);    // 16 x 128
        gemm_h16<<<g, 256, GSMEM1>>>(phi, wthi, out, DF, DF, DM, DF / 32);
    }
}

// round 17
// speedup vs baseline: 1.0536x; 1.0357x over previous
#include <cuda_runtime.h>
#include <cuda_fp16.h>
#include <cstdint>
#include <math_constants.h>

// Problem dims (fixed per reference)
#define DM   1024      // d_model
#define DF   4096      // d_ff
#define MROWS 16384    // 4 * 4096

// ---------------------------------------------------------------------------
// Scratch (allocation-free: __device__ globals)
// ---------------------------------------------------------------------------
__device__ float  g_scores[(size_t)MROWS * DF];   // 256 MB fp32 logits
__device__ __half g_phi[(size_t)MROWS * DF];      // probs (single fp16)
__device__ __half g_xhi[(size_t)MROWS * DM];      // rmsnorm(x) hi
__device__ __half g_xlo[(size_t)MROWS * DM];      // rmsnorm(x) lo
__device__ __half g_whi[(size_t)DF * DM];         // rmsnorm(w) hi
__device__ __half g_wlo[(size_t)DF * DM];         // rmsnorm(w) lo
__device__ __half g_wthi[(size_t)DM * DF];        // W^T (raw w) [d][c]

// ---------------------------------------------------------------------------
// PTX helpers
// ---------------------------------------------------------------------------
__device__ __forceinline__ uint32_t smem_u32_of(const void* p) {
    uint32_t a;
    asm("{ .reg .u64 t; cvta.to.shared.u64 t, %1; cvt.u32.u64 %0, t; }" : "=r"(a) : "l"(p));
    return a;
}

__device__ __forceinline__ void cp16(uint32_t s, const void* g) {
    asm volatile("cp.async.cg.shared.global [%0], [%1], 16;" :: "r"(s), "l"(g));
}

__device__ __forceinline__ void ldsm4(uint32_t* r, uint32_t a) {
    asm volatile("ldmatrix.sync.aligned.m8n8.x4.shared.b16 {%0,%1,%2,%3}, [%4];"
                 : "=r"(r[0]), "=r"(r[1]), "=r"(r[2]), "=r"(r[3]) : "r"(a));
}

__device__ __forceinline__ void mma16816(float* d, const uint32_t* a, const uint32_t* b) {
    asm volatile(
        "mma.sync.aligned.m16n8k16.row.col.f32.f16.f16.f32 "
        "{%0,%1,%2,%3}, {%4,%5,%6,%7}, {%8,%9}, {%0,%1,%2,%3};"
        : "+f"(d[0]), "+f"(d[1]), "+f"(d[2]), "+f"(d[3])
        : "r"(a[0]), "r"(a[1]), "r"(a[2]), "r"(a[3]), "r"(b[0]), "r"(b[1]));
}

// f16-accumulator variant (2-reg D fragment; same thread/element mapping)
__device__ __forceinline__ void mma16816h(uint32_t* d, const uint32_t* a, const uint32_t* b) {
    asm volatile(
        "mma.sync.aligned.m16n8k16.row.col.f16.f16.f16.f16 "
        "{%0,%1}, {%2,%3,%4,%5}, {%6,%7}, {%0,%1};"
        : "+r"(d[0]), "+r"(d[1])
        : "r"(a[0]), "r"(a[1]), "r"(a[2]), "r"(a[3]), "r"(b[0]), "r"(b[1]));
}

// ---------------------------------------------------------------------------
// Kernel: fused per-row rmsnorm + fp16 hi/lo split for BOTH x and w.
// Blocks [0, MROWS) -> x rows; blocks [MROWS, MROWS+DF) -> w rows.
// ---------------------------------------------------------------------------
__device__ __forceinline__ void split2h(float v, __half& h, __half& l) {
    h = __float2half_rn(v);
    l = __float2half_rn(v - __half2float(h));
}

__global__ __launch_bounds__(256) void rms_split_all(
    const float* __restrict__ x, const float* __restrict__ w,
    __half* __restrict__ xhi, __half* __restrict__ xlo,
    __half* __restrict__ whi, __half* __restrict__ wlo)
{
    const int blk = blockIdx.x;
    const bool isW = blk >= MROWS;
    const int row = isW ? (blk - MROWS) : blk;
    const float* src = isW ? w : x;
    __half* hi = isW ? whi : xhi;
    __half* lo = isW ? wlo : xlo;

    const int tid = threadIdx.x;
    const size_t base = (size_t)row * DM;

    float4 v = *(const float4*)(src + base + tid * 4);
    float ss = v.x * v.x + v.y * v.y + v.z * v.z + v.w * v.w;

    __shared__ float red[256];
    red[tid] = ss;
    __syncthreads();
    #pragma unroll
    for (int off = 128; off > 0; off >>= 1) {
        if (tid < off) red[tid] += red[tid + off];
        __syncthreads();
    }
    const float s = rsqrtf(red[0] * (1.0f / DM) + 1e-6f);

    __half h0, h1, h2, h3, l0, l1, l2, l3;
    split2h(v.x * s, h0, l0); split2h(v.y * s, h1, l1);
    split2h(v.z * s, h2, l2); split2h(v.w * s, h3, l3);
    __half2* H = (__half2*)(hi + base + tid * 4);
    __half2* L = (__half2*)(lo + base + tid * 4);
    H[0] = __halves2half2(h0, h1); H[1] = __halves2half2(h2, h3);
    L[0] = __halves2half2(l0, l1); L[1] = __halves2half2(l2, l3);
}

// ---------------------------------------------------------------------------
// Kernel: transpose  W[c,d] -> Wt[d,c]  (raw w, single fp16)
// ---------------------------------------------------------------------------
__global__ void wt_kernel(const float* __restrict__ w, __half* __restrict__ th)
{
    __shared__ float t[32][33];
    const int c = blockIdx.y * 32 + threadIdx.y;
    const int d = blockIdx.x * 32 + threadIdx.x;
    t[threadIdx.y][threadIdx.x] = w[(size_t)c * DM + d];
    __syncthreads();
    const int dd = blockIdx.x * 32 + threadIdx.y;
    const int cc = blockIdx.y * 32 + threadIdx.x;
    th[(size_t)dd * DF + cc] = __float2half_rn(t[threadIdx.x][threadIdx.y]);
}

// ---------------------------------------------------------------------------
// Kernel: row softmax over 4096, emits single fp16 probs.
// COALESCED layout: thread t handles columns t + j*256 (warp = 128B/load).
// ---------------------------------------------------------------------------
__global__ __launch_bounds__(256) void softmax_h(const float* __restrict__ S,
                                                 __half* __restrict__ PH)
{
    const int row = blockIdx.x;
    const int tid = threadIdx.x;
    const float* p = S + (size_t)row * DF;

    float v[16];
    float lm = -CUDART_INF_F;
    #pragma unroll
    for (int j = 0; j < 16; j++) {
        v[j] = p[tid + j * 256];
        lm = fmaxf(lm, v[j]);
    }

    __shared__ float red[256];
    red[tid] = lm;
    __syncthreads();
    #pragma unroll
    for (int off = 128; off > 0; off >>= 1) {
        if (tid < off) red[tid] = fmaxf(red[tid], red[tid + off]);
        __syncthreads();
    }
    const float m = red[0];
    __syncthreads();

    float ls = 0.f;
    #pragma unroll
    for (int j = 0; j < 16; j++) {
        v[j] = __expf(v[j] - m);
        ls += v[j];
    }
    red[tid] = ls;
    __syncthreads();
    #pragma unroll
    for (int off = 128; off > 0; off >>= 1) {
        if (tid < off) red[tid] += red[tid + off];
        __syncthreads();
    }
    const float inv = 1.0f / red[0];

    __half* ph = PH + (size_t)row * DF;
    #pragma unroll
    for (int j = 0; j < 16; j++)
        ph[tid + j * 256] = __float2half_rn(v[j] * inv);
}

// ---------------------------------------------------------------------------
// GEMM1: split-fp16 NT GEMM, 256 threads / 8 warps, warp grid 4x2 (tile 32x32).
//   main  : Ah*Bh  f32 acc;  cross: Ah*Bl + Al*Bh shared f16 acc.
// CTA 128x64, BK=32, 3-stage cp.async ring -> 92 KB smem => 2 CTAs per SM.
// Stage 30720 B: Ah(128x80)@0 | Al@10240 | Bh(64x80)@20480 | Bl@25600.
// ---------------------------------------------------------------------------
#define APL  10240                   // A plane bytes (128 x 80)
#define BPL  5120                    // B plane bytes (64 x 80)
#define STG  (2 * APL + 2 * BPL)     // 30720
#define GSMEM (3 * STG)              // 92160

__global__ __launch_bounds__(256, 2) void gemm_hsplit(
    const __half* __restrict__ Ah, const __half* __restrict__ Al,
    const __half* __restrict__ Bh, const __half* __restrict__ Bl,
    float* __restrict__ C, int lda, int ldb, int ldc, int KT)
{
    extern __shared__ __align__(16) char smem[];
    const uint32_t sbase = smem_u32_of(smem);
    const int tid  = threadIdx.x;
    const int lane = tid & 31;
    const int wid  = tid >> 5;           // 0..7
    const int wm   = (wid >> 1) * 32;    // 0,32,64,96
    const int wn   = (wid & 1) * 32;     // 0,32
    const int bm   = blockIdx.y * 128;
    const int bn   = blockIdx.x * 64;

    const int lr = tid >> 2;             // 0..63
    const int lc = tid & 3;              // 16B chunk
    const __half* pAh = Ah + (size_t)(bm + lr) * lda + lc * 8;
    const __half* pAl = Al + (size_t)(bm + lr) * lda + lc * 8;
    const __half* pBh = Bh + (size_t)(bn + lr) * ldb + lc * 8;
    const __half* pBl = Bl + (size_t)(bn + lr) * ldb + lc * 8;
    const size_t rstepA = (size_t)64 * lda;
    const uint32_t so = lr * 80 + lc * 16;

    float    accm[2][4][4];   // hi*hi, f32 acc
    uint32_t accx[2][4][2];   // cross, f16 acc
    #pragma unroll
    for (int i = 0; i < 2; i++)
        #pragma unroll
        for (int j = 0; j < 4; j++) {
            #pragma unroll
            for (int k = 0; k < 4; k++) accm[i][j][k] = 0.f;
            accx[i][j][0] = 0u; accx[i][j][1] = 0u;
        }

#define LOAD_STAGE(kt, slot)                                                  \
    do {                                                                      \
        const int _k0 = (kt) * 32;                                            \
        const uint32_t _sb = sbase + (slot) * STG + so;                       \
        cp16(_sb + 0,           pAh + _k0);                                   \
        cp16(_sb + 5120,        pAh + _k0 + rstepA);                          \
        cp16(_sb + APL,         pAl + _k0);                                   \
        cp16(_sb + APL + 5120,  pAl + _k0 + rstepA);                          \
        cp16(_sb + 2 * APL,       pBh + _k0);                                 \
        cp16(_sb + 2 * APL + BPL, pBl + _k0);                                 \
    } while (0)

    LOAD_STAGE(0, 0); asm volatile("cp.async.commit_group;" ::: "memory");
    LOAD_STAGE(1, 1); asm volatile("cp.async.commit_group;" ::: "memory");

    const uint32_t aoff = ((wm + (lane & 15)) * 40 + ((lane >> 4) << 3)) * 2;
    const uint32_t boff = ((wn + (lane & 7) + ((lane >> 4) << 3)) * 40 + (lane & 8)) * 2;

    int slot = 0, nslot = 2;
    for (int kt = 0; kt < KT; ++kt) {
        asm volatile("cp.async.wait_group 1;" ::: "memory");
        __syncthreads();
        const uint32_t sb = sbase + slot * STG;

        #pragma unroll
        for (int ks = 0; ks < 2; ++ks) {
            const uint32_t kc2 = ks * 32;
            uint32_t ahf[2][4], alf[2][4], bhf[4][2], blf[4][2];
            #pragma unroll
            for (int mt = 0; mt < 2; mt++) {
                ldsm4(ahf[mt], sb + aoff + kc2 + mt * 1280);
                ldsm4(alf[mt], sb + APL + aoff + kc2 + mt * 1280);
            }
            #pragma unroll
            for (int n2 = 0; n2 < 2; n2++) {
                uint32_t r[4];
                ldsm4(r, sb + 2 * APL + boff + kc2 + n2 * 1280);
                bhf[n2 * 2][0] = r[0]; bhf[n2 * 2][1] = r[1];
                bhf[n2 * 2 + 1][0] = r[2]; bhf[n2 * 2 + 1][1] = r[3];
                ldsm4(r, sb + 2 * APL + BPL + boff + kc2 + n2 * 1280);
                blf[n2 * 2][0] = r[0]; blf[n2 * 2][1] = r[1];
                blf[n2 * 2 + 1][0] = r[2]; blf[n2 * 2 + 1][1] = r[3];
            }
            #pragma unroll
            for (int mt = 0; mt < 2; mt++)
                #pragma unroll
                for (int nt = 0; nt < 4; nt++) {
                    mma16816(accm[mt][nt], ahf[mt], bhf[nt]);    // hi*hi (f32)
                    mma16816h(accx[mt][nt], ahf[mt], blf[nt]);   // hi*lo (f16)
                    mma16816h(accx[mt][nt], alf[mt], bhf[nt]);   // lo*hi (f16)
                }
        }
        if (kt + 2 < KT) LOAD_STAGE(kt + 2, nslot);
        asm volatile("cp.async.commit_group;" ::: "memory");
        slot = (slot == 2) ? 0 : slot + 1;
        nslot = (nslot == 2) ? 0 : nslot + 1;
    }

    #pragma unroll
    for (int mt = 0; mt < 2; mt++) {
        const int row = bm + wm + mt * 16 + (lane >> 2);
        float* r0 = C + (size_t)row * ldc + bn + wn + (lane & 3) * 2;
        float* r1 = r0 + (size_t)8 * ldc;
        #pragma unroll
        for (int nt = 0; nt < 4; nt++) {
            const __half2 x01 = *reinterpret_cast<const __half2*>(&accx[mt][nt][0]);
            const __half2 x23 = *reinterpret_cast<const __half2*>(&accx[mt][nt][1]);
            *(float2*)(r0 + nt * 8) = make_float2(
                accm[mt][nt][0] + __low2float(x01),
                accm[mt][nt][1] + __high2float(x01));
            *(float2*)(r1 + nt * 8) = make_float2(
                accm[mt][nt][2] + __low2float(x23),
                accm[mt][nt][3] + __high2float(x23));
        }
    }
#undef LOAD_STAGE
}

// ---------------------------------------------------------------------------
// GEMM2: single-fp16 NT GEMM (1 term, f32 acc), 256 threads, CTA 128x64.
// BK=32, 4-stage ring -> 61 KB smem => 2+ CTAs per SM.
// Stage 15360 B: A(128x80)@0 | B(64x80)@10240.
// ---------------------------------------------------------------------------
#define STG1   (APL + BPL)       // 15360
#define GSMEM1 (4 * STG1)        // 61440

__global__ __launch_bounds__(256, 2) void gemm_h16(
    const __half* __restrict__ A, const __half* __restrict__ B,
    float* __restrict__ C, int lda, int ldb, int ldc, int KT)
{
    extern __shared__ __align__(16) char smem[];
    const uint32_t sbase = smem_u32_of(smem);
    const int tid  = threadIdx.x;
    const int lane = tid & 31;
    const int wid  = tid >> 5;
    const int wm   = (wid >> 1) * 32;
    const int wn   = (wid & 1) * 32;
    const int bm   = blockIdx.y * 128;
    const int bn   = blockIdx.x * 64;

    const int lr = tid >> 2;
    const int lc = tid & 3;
    const __half* pA = A + (size_t)(bm + lr) * lda + lc * 8;
    const __half* pB = B + (size_t)(bn + lr) * ldb + lc * 8;
    const size_t rstepA = (size_t)64 * lda;
    const uint32_t so = lr * 80 + lc * 16;

    float acc[2][4][4];
    #pragma unroll
    for (int i = 0; i < 2; i++)
        #pragma unroll
        for (int j = 0; j < 4; j++)
            #pragma unroll
            for (int k = 0; k < 4; k++) acc[i][j][k] = 0.f;

#define LOAD_S1(kt)                                                           \
    do {                                                                      \
        const int _k0 = (kt) * 32;                                            \
        const uint32_t _sb = sbase + ((kt) & 3) * STG1 + so;                  \
        cp16(_sb + 0,    pA + _k0);                                           \
        cp16(_sb + 5120, pA + _k0 + rstepA);                                  \
        cp16(_sb + APL,  pB + _k0);                                           \
    } while (0)

    LOAD_S1(0); asm volatile("cp.async.commit_group;" ::: "memory");
    LOAD_S1(1); asm volatile("cp.async.commit_group;" ::: "memory");
    LOAD_S1(2); asm volatile("cp.async.commit_group;" ::: "memory");

    const uint32_t aoff = ((wm + (lane & 15)) * 40 + ((lane >> 4) << 3)) * 2;
    const uint32_t boff = ((wn + (lane & 7) + ((lane >> 4) << 3)) * 40 + (lane & 8)) * 2;

    for (int kt = 0; kt < KT; ++kt) {
        asm volatile("cp.async.wait_group 2;" ::: "memory");
        __syncthreads();
        const uint32_t sb = sbase + (kt & 3) * STG1;

        #pragma unroll
        for (int ks = 0; ks < 2; ++ks) {
            const uint32_t kc2 = ks * 32;
            uint32_t af[2][4], bf[4][2];
            #pragma unroll
            for (int mt = 0; mt < 2; mt++)
                ldsm4(af[mt], sb + aoff + kc2 + mt * 1280);
            #pragma unroll
            for (int n2 = 0; n2 < 2; n2++) {
                uint32_t r[4];
                ldsm4(r, sb + APL + boff + kc2 + n2 * 1280);
                bf[n2 * 2][0] = r[0]; bf[n2 * 2][1] = r[1];
                bf[n2 * 2 + 1][0] = r[2]; bf[n2 * 2 + 1][1] = r[3];
            }
            #pragma unroll
            for (int mt = 0; mt < 2; mt++)
                #pragma unroll
                for (int nt = 0; nt < 4; nt++)
                    mma16816(acc[mt][nt], af[mt], bf[nt]);
        }
        __syncthreads();
        if (kt + 3 < KT) LOAD_S1(kt + 3);
        asm volatile("cp.async.commit_group;" ::: "memory");
    }

    #pragma unroll
    for (int mt = 0; mt < 2; mt++) {
        const int row = bm + wm + mt * 16 + (lane >> 2);
        float* r0 = C + (size_t)row * ldc + bn + wn + (lane & 3) * 2;
        float* r1 = r0 + (size_t)8 * ldc;
        #pragma unroll
        for (int nt = 0; nt < 4; nt++) {
            *(float2*)(r0 + nt * 8) = make_float2(acc[mt][nt][0], acc[mt][nt][1]);
            *(float2*)(r1 + nt * 8) = make_float2(acc[mt][nt][2], acc[mt][nt][3]);
        }
    }
#undef LOAD_S1
}

// ---------------------------------------------------------------------------
// Launch (single stream)
// ---------------------------------------------------------------------------
extern "C" void kernel_launch(void* const* d_in, const int* in_sizes, int n_in,
                              void* d_out, int out_size)
{
    const float* x = (const float*)d_in[0];   // [16384, 1024]
    const float* w = (const float*)d_in[1];   // [4096, 1024]
    float* out = (float*)d_out;               // [16384, 1024]

    float *scores;
    __half *xhi, *xlo, *whi, *wlo, *wthi, *phi;
    cudaGetSymbolAddress((void**)&scores, g_scores);
    cudaGetSymbolAddress((void**)&xhi, g_xhi);
    cudaGetSymbolAddress((void**)&xlo, g_xlo);
    cudaGetSymbolAddress((void**)&whi, g_whi);
    cudaGetSymbolAddress((void**)&wlo, g_wlo);
    cudaGetSymbolAddress((void**)&wthi, g_wthi);
    cudaGetSymbolAddress((void**)&phi, g_phi);

    cudaFuncSetAttribute(gemm_hsplit, cudaFuncAttributeMaxDynamicSharedMemorySize,
                         GSMEM);
    cudaFuncSetAttribute(gemm_h16, cudaFuncAttributeMaxDynamicSharedMemorySize,
                         GSMEM1);

    // Prep: fused rmsnorm + fp16 hi/lo splits for x AND w in one launch
    rms_split_all<<<MROWS + DF, 256>>>(x, w, xhi, xlo, whi, wlo);
    {
        dim3 g(DM / 32, DF / 32), b(32, 32);
        wt_kernel<<<g, b>>>(w, wthi);
    }

    // GEMM1 (hi*hi f32 acc + cross f16 acc): scores
    {
        dim3 g(DF / 64, MROWS / 128);    // 64 x 128
        gemm_hsplit<<<g, 256, GSMEM>>>(xhi, xlo, whi, wlo, scores,
                                       DM, DM, DF, DM / 32);
    }

    // softmax rows -> fp16 probs
    softmax_h<<<MROWS, 256>>>(scores, phi);

    // GEMM2 (1-term fp16, f32 acc)
    {
        dim3 g(DM / 64, MROWS / 128);    // 16 x 128
        gemm_h16<<<g, 256, GSMEM1>>>(phi, wthi, out, DF, DF, DM, DF / 32);
    }
}